// round 5
// baseline (speedup 1.0000x reference)
#include <cuda_runtime.h>
#include <cuda_bf16.h>

#define NF    13776
#define KC    8
#define CHUNK 256                       // faces staged in smem (covers 8th-valid ~always)
#define RPB   64                        // receivers per block
#define NT    256
#define NBLK  ((NF + RPB - 1) / RPB)    // 216 blocks

__device__ float g_partial[NBLK];

// ---------------- cone-field penalty (matches jnp fp32 math) ----------------
// SIGMA=0.5 -> r/SIGMA=2r, h/SIGMA=2h. POINT2PLANE=False, PENALIZE_OUTSIDE=True.
__device__ __forceinline__ float cone_pen(const float* __restrict__ s,
                                          const float* __restrict__ p) {
    float e0x = s[3] - s[0], e0y = s[4] - s[1], e0z = s[5] - s[2];
    float e1x = s[6] - s[0], e1y = s[7] - s[1], e1z = s[8] - s[2];
    float nx = e0y * e1z - e0z * e1y;
    float ny = e0z * e1x - e0x * e1z;
    float nz = e0x * e1y - e0y * e1x;
    float inv = 1.0f / (sqrtf(nx * nx + ny * ny + nz * nz) + 1e-8f);
    nx *= inv; ny *= inv; nz *= inv;
    float cx = (s[0] + s[3] + s[6]) * (1.0f / 3.0f);
    float cy = (s[1] + s[4] + s[7]) * (1.0f / 3.0f);
    float cz = (s[2] + s[5] + s[8]) * (1.0f / 3.0f);

    float acc = 0.0f;
#pragma unroll
    for (int v = 0; v < 3; ++v) {
        float ux = p[3 * v + 0] - cx;
        float uy = p[3 * v + 1] - cy;
        float uz = p[3 * v + 2] - cz;
        float h = ux * nx + uy * ny + uz * nz;
        float wx = ux - h * nx, wy = uy - h * ny, wz = uz - h * nz;
        float r = sqrtf(wx * wx + wy * wy + wz * wz);
        float radial = fmaxf(1.0f - 2.0f * r, 0.0f);
        float depth  = fmaxf(-h, 0.0f) + fmaxf(h, 0.0f) * __expf(-2.0f * h);
        float phi = radial * depth;
        acc += phi * phi;
    }
    return acc;
}

__device__ __forceinline__ float min3(float a, float b, float c) { return fminf(a, fminf(b, c)); }
__device__ __forceinline__ float max3(float a, float b, float c) { return fmaxf(a, fmaxf(b, c)); }

// ---------------- main kernel: self-sufficient block ----------------
__global__ void __launch_bounds__(NT)
main_kernel(const float* __restrict__ verts,
            const int*   __restrict__ faces) {
    __shared__ float sJmin[3][CHUNK];
    __shared__ float sJmax[3][CHUNK];
    __shared__ int   sJf[3][CHUNK];
    __shared__ float sJtri[CHUNK][12];   // padded stride 12 (bank spread)
    __shared__ float sRtri[RPB][12];
    __shared__ int   sPairs[RPB][KC];

    const int t = threadIdx.x;
    const int blockBase = blockIdx.x * RPB;

    // ---- phase 1a: every thread stages one chunk face ----
    {
        int c = t;   // CHUNK == NT
        int i0 = faces[3 * c + 0];
        int i1 = faces[3 * c + 1];
        int i2 = faces[3 * c + 2];
        float ax = verts[3 * i0 + 0], ay = verts[3 * i0 + 1], az = verts[3 * i0 + 2];
        float bx = verts[3 * i1 + 0], by = verts[3 * i1 + 1], bz = verts[3 * i1 + 2];
        float cx = verts[3 * i2 + 0], cy = verts[3 * i2 + 1], cz = verts[3 * i2 + 2];
        sJf[0][c] = i0; sJf[1][c] = i1; sJf[2][c] = i2;
        float* tr = sJtri[c];
        tr[0] = ax; tr[1] = ay; tr[2] = az;
        tr[3] = bx; tr[4] = by; tr[5] = bz;
        tr[6] = cx; tr[7] = cy; tr[8] = cz;
        sJmin[0][c] = min3(ax, bx, cx); sJmax[0][c] = max3(ax, bx, cx);
        sJmin[1][c] = min3(ay, by, cy); sJmax[1][c] = max3(ay, by, cy);
        sJmin[2][c] = min3(az, bz, cz); sJmax[2][c] = max3(az, bz, cz);
    }

    // ---- phase 1b: threads [0,RPB) stage their receiver ----
    float rlx = 0, rly = 0, rlz = 0, rhx = 0, rhy = 0, rhz = 0;
    int rf0 = -1, rf1 = -2, rf2 = -3;
    bool rvalid = false;
    if (t < RPB && (blockBase + t) < NF) {
        int rg = blockBase + t;
        rf0 = faces[3 * rg + 0];
        rf1 = faces[3 * rg + 1];
        rf2 = faces[3 * rg + 2];
        float ax = verts[3 * rf0 + 0], ay = verts[3 * rf0 + 1], az = verts[3 * rf0 + 2];
        float bx = verts[3 * rf1 + 0], by = verts[3 * rf1 + 1], bz = verts[3 * rf1 + 2];
        float cx = verts[3 * rf2 + 0], cy = verts[3 * rf2 + 1], cz = verts[3 * rf2 + 2];
        float* tr = sRtri[t];
        tr[0] = ax; tr[1] = ay; tr[2] = az;
        tr[3] = bx; tr[4] = by; tr[5] = bz;
        tr[6] = cx; tr[7] = cy; tr[8] = cz;
        rlx = min3(ax, bx, cx); rhx = max3(ax, bx, cx);
        rly = min3(ay, by, cy); rhy = max3(ay, by, cy);
        rlz = min3(az, bz, cz); rhz = max3(az, bz, cz);
        rvalid = true;
    }
    __syncthreads();

    // ---- phase 2: broad (thread per receiver, first-KC ascending j) ----
    if (t < RPB) {
        int cnt = 0;
        if (rvalid) {
            for (int j = 0; j < CHUNK && cnt < KC; ++j) {
                bool ok = (rlx <= sJmax[0][j]) & (sJmin[0][j] <= rhx) &
                          (rly <= sJmax[1][j]) & (sJmin[1][j] <= rhy) &
                          (rlz <= sJmax[2][j]) & (sJmin[2][j] <= rhz);
                if (ok) {
                    int j0 = sJf[0][j], j1 = sJf[1][j], j2 = sJf[2][j];
                    bool share = (rf0 == j0) | (rf0 == j1) | (rf0 == j2) |
                                 (rf1 == j0) | (rf1 == j1) | (rf1 == j2) |
                                 (rf2 == j0) | (rf2 == j1) | (rf2 == j2);
                    if (!share) sPairs[t][cnt++] = j;
                }
            }
            // exactness fallback: scan remaining faces from global (almost never taken)
            for (int j = CHUNK; j < NF && cnt < KC; ++j) {
                int j0 = __ldg(&faces[3 * j + 0]);
                int j1 = __ldg(&faces[3 * j + 1]);
                int j2 = __ldg(&faces[3 * j + 2]);
                float ax = __ldg(&verts[3 * j0 + 0]), ay = __ldg(&verts[3 * j0 + 1]), az = __ldg(&verts[3 * j0 + 2]);
                float bx = __ldg(&verts[3 * j1 + 0]), by = __ldg(&verts[3 * j1 + 1]), bz = __ldg(&verts[3 * j1 + 2]);
                float cx = __ldg(&verts[3 * j2 + 0]), cy = __ldg(&verts[3 * j2 + 1]), cz = __ldg(&verts[3 * j2 + 2]);
                float jlx = min3(ax, bx, cx), jhx = max3(ax, bx, cx);
                float jly = min3(ay, by, cy), jhy = max3(ay, by, cy);
                float jlz = min3(az, bz, cz), jhz = max3(az, bz, cz);
                bool ok = (rlx <= jhx) & (jlx <= rhx) &
                          (rly <= jhy) & (jly <= rhy) &
                          (rlz <= jhz) & (jlz <= rhz);
                if (ok) {
                    bool share = (rf0 == j0) | (rf0 == j1) | (rf0 == j2) |
                                 (rf1 == j0) | (rf1 == j1) | (rf1 == j2) |
                                 (rf2 == j0) | (rf2 == j1) | (rf2 == j2);
                    if (!share) sPairs[t][cnt++] = j;
                }
            }
        }
        for (int k = cnt; k < KC; ++k) sPairs[t][k] = -1;
    }
    __syncthreads();

    // ---- phase 3: narrow — RPB*KC tasks redistributed over all threads ----
    float acc = 0.0f;
#pragma unroll
    for (int q = 0; q < (RPB * KC) / NT; ++q) {   // 2 tasks/thread
        int s = t + q * NT;
        int r = s >> 3;        // receiver slot in block
        int k = s & 7;
        if ((blockBase + r) < NF) {
            int j = sPairs[r][k];
            if (j >= 0) {
                float a[9], b[9];
                const float* ap = sRtri[r];
#pragma unroll
                for (int x = 0; x < 9; ++x) a[x] = ap[x];
                if (j < CHUNK) {
                    const float* bp = sJtri[j];
#pragma unroll
                    for (int x = 0; x < 9; ++x) b[x] = bp[x];
                } else {
                    int j0 = __ldg(&faces[3 * j + 0]);
                    int j1 = __ldg(&faces[3 * j + 1]);
                    int j2 = __ldg(&faces[3 * j + 2]);
                    b[0] = __ldg(&verts[3 * j0 + 0]); b[1] = __ldg(&verts[3 * j0 + 1]); b[2] = __ldg(&verts[3 * j0 + 2]);
                    b[3] = __ldg(&verts[3 * j1 + 0]); b[4] = __ldg(&verts[3 * j1 + 1]); b[5] = __ldg(&verts[3 * j1 + 2]);
                    b[6] = __ldg(&verts[3 * j2 + 0]); b[7] = __ldg(&verts[3 * j2 + 1]); b[8] = __ldg(&verts[3 * j2 + 2]);
                }
                acc += cone_pen(a, b) + cone_pen(b, a);
            }
        }
    }

    // ---- phase 4: block reduce -> partial (deterministic per block) ----
    const int lane = t & 31;
    const int w    = t >> 5;
#pragma unroll
    for (int off = 16; off > 0; off >>= 1)
        acc += __shfl_down_sync(0xffffffffu, acc, off);

    __shared__ float ssum[NT / 32];
    if (lane == 0) ssum[w] = acc;
    __syncthreads();
    if (w == 0) {
        float v = (lane < (NT / 32)) ? ssum[lane] : 0.0f;
#pragma unroll
        for (int off = 4; off > 0; off >>= 1)
            v += __shfl_down_sync(0xffffffffu, v, off);
        if (lane == 0) g_partial[blockIdx.x] = v;
    }
}

// ---------------- reduce kernel: fixed-order sum of partials ----------------
__global__ void reduce_kernel(float* __restrict__ out) {
    int t = threadIdx.x;
    float acc = (t < NBLK) ? g_partial[t] : 0.0f;
    const int lane = t & 31;
    const int w    = t >> 5;
#pragma unroll
    for (int off = 16; off > 0; off >>= 1)
        acc += __shfl_down_sync(0xffffffffu, acc, off);
    __shared__ float ssum[8];
    if (lane == 0) ssum[w] = acc;
    __syncthreads();
    if (w == 0) {
        float v = (lane < 8) ? ssum[lane] : 0.0f;
#pragma unroll
        for (int off = 4; off > 0; off >>= 1)
            v += __shfl_down_sync(0xffffffffu, v, off);
        if (lane == 0) out[0] = v;
    }
}

// ---------------- launch ----------------
extern "C" void kernel_launch(void* const* d_in, const int* in_sizes, int n_in,
                              void* d_out, int out_size) {
    const float* verts = (const float*)d_in[0];
    const int*   faces = (const int*)d_in[1];
    float* out = (float*)d_out;

    main_kernel<<<NBLK, NT>>>(verts, faces);
    reduce_kernel<<<1, 256>>>(out);
}

// round 6
// speedup vs baseline: 1.6208x; 1.6208x over previous
#include <cuda_runtime.h>
#include <cuda_bf16.h>

#define NF   13776
#define KC   8
#define NT   256
#define WPB  (NT / 32)            // 8 warps (receivers) per block
#define NBLK (NF / WPB)           // 1722 blocks, exact

__device__ float    g_partial[NBLK];
__device__ unsigned g_done = 0;   // self-resetting ticket counter

__device__ __forceinline__ float min3(float a, float b, float c) { return fminf(a, fminf(b, c)); }
__device__ __forceinline__ float max3(float a, float b, float c) { return fmaxf(a, fmaxf(b, c)); }

// ---------------- cone-field penalty (matches jnp fp32 math) ----------------
// SIGMA=0.5 -> r/SIGMA=2r, h/SIGMA=2h. POINT2PLANE=False, PENALIZE_OUTSIDE=True.
__device__ __forceinline__ float cone_pen(const float* __restrict__ s,
                                          const float* __restrict__ p) {
    float e0x = s[3] - s[0], e0y = s[4] - s[1], e0z = s[5] - s[2];
    float e1x = s[6] - s[0], e1y = s[7] - s[1], e1z = s[8] - s[2];
    float nx = e0y * e1z - e0z * e1y;
    float ny = e0z * e1x - e0x * e1z;
    float nz = e0x * e1y - e0y * e1x;
    float inv = 1.0f / (sqrtf(nx * nx + ny * ny + nz * nz) + 1e-8f);
    nx *= inv; ny *= inv; nz *= inv;
    float cx = (s[0] + s[3] + s[6]) * (1.0f / 3.0f);
    float cy = (s[1] + s[4] + s[7]) * (1.0f / 3.0f);
    float cz = (s[2] + s[5] + s[8]) * (1.0f / 3.0f);

    float acc = 0.0f;
#pragma unroll
    for (int v = 0; v < 3; ++v) {
        float ux = p[3 * v + 0] - cx;
        float uy = p[3 * v + 1] - cy;
        float uz = p[3 * v + 2] - cz;
        float h = ux * nx + uy * ny + uz * nz;
        float wx = ux - h * nx, wy = uy - h * ny, wz = uz - h * nz;
        float r = sqrtf(wx * wx + wy * wy + wz * wz);
        float radial = fmaxf(1.0f - 2.0f * r, 0.0f);
        float depth  = fmaxf(-h, 0.0f) + fmaxf(h, 0.0f) * expf(-2.0f * h);
        float phi = radial * depth;
        acc += phi * phi;
    }
    return acc;
}

// load the 9 coords of face f (assumes f in range)
__device__ __forceinline__ void load_tri(const float* __restrict__ verts,
                                         const int*   __restrict__ faces,
                                         int f, float* tr, int* id) {
    int i0 = faces[3 * f + 0];
    int i1 = faces[3 * f + 1];
    int i2 = faces[3 * f + 2];
    id[0] = i0; id[1] = i1; id[2] = i2;
    tr[0] = verts[3 * i0 + 0]; tr[1] = verts[3 * i0 + 1]; tr[2] = verts[3 * i0 + 2];
    tr[3] = verts[3 * i1 + 0]; tr[4] = verts[3 * i1 + 1]; tr[5] = verts[3 * i1 + 2];
    tr[6] = verts[3 * i2 + 0]; tr[7] = verts[3 * i2 + 1]; tr[8] = verts[3 * i2 + 2];
}

// ---------------- single fused kernel ----------------
__global__ void __launch_bounds__(NT)
fused_kernel(const float* __restrict__ verts,
             const int*   __restrict__ faces,
             float* __restrict__ out) {
    const int t    = threadIdx.x;
    const int lane = t & 31;
    const int w    = t >> 5;
    const int i    = blockIdx.x * WPB + w;       // receiver face (always < NF)

    __shared__ int   sPairs[WPB][KC];
    __shared__ float ssum[WPB];
    __shared__ bool  sLast;

    // ---- receiver: all lanes load the same face (broadcast loads) ----
    float ri[9]; int fi[3];
    load_tri(verts, faces, i, ri, fi);
    float rlx = min3(ri[0], ri[3], ri[6]), rhx = max3(ri[0], ri[3], ri[6]);
    float rly = min3(ri[1], ri[4], ri[7]), rhy = max3(ri[1], ri[4], ri[7]);
    float rlz = min3(ri[2], ri[5], ri[8]), rhz = max3(ri[2], ri[5], ri[8]);

    // ---- broad phase: warp ballot scan, first-KC ascending j ----
    int cnt = 0;
    for (int base = 0; base < NF && cnt < KC; base += 32) {
        int j = base + lane;
        bool ok = false;
        if (j < NF) {
            int j0 = faces[3 * j + 0];
            int j1 = faces[3 * j + 1];
            int j2 = faces[3 * j + 2];
            float ax = verts[3 * j0 + 0], ay = verts[3 * j0 + 1], az = verts[3 * j0 + 2];
            float bx = verts[3 * j1 + 0], by = verts[3 * j1 + 1], bz = verts[3 * j1 + 2];
            float cx = verts[3 * j2 + 0], cy = verts[3 * j2 + 1], cz = verts[3 * j2 + 2];
            float jlx = min3(ax, bx, cx), jhx = max3(ax, bx, cx);
            float jly = min3(ay, by, cy), jhy = max3(ay, by, cy);
            float jlz = min3(az, bz, cz), jhz = max3(az, bz, cz);
            ok = (rlx <= jhx) & (jlx <= rhx) &
                 (rly <= jhy) & (jly <= rhy) &
                 (rlz <= jhz) & (jlz <= rhz);
            if (ok) {
                bool share = (fi[0] == j0) | (fi[0] == j1) | (fi[0] == j2) |
                             (fi[1] == j0) | (fi[1] == j1) | (fi[1] == j2) |
                             (fi[2] == j0) | (fi[2] == j1) | (fi[2] == j2);
                ok = !share;
            }
        }
        unsigned m = __ballot_sync(0xffffffffu, ok);
        int rank = __popc(m & ((1u << lane) - 1u));
        if (ok && (cnt + rank) < KC)
            sPairs[w][cnt + rank] = j;
        cnt = min(KC, cnt + __popc(m));
    }
    if (lane < KC && lane >= cnt)
        sPairs[w][lane] = -1;
    __syncwarp();

    // ---- narrow phase: lane l<16 -> (pair l>>1, direction l&1) ----
    float acc = 0.0f;
    if (lane < 2 * KC) {
        int j = sPairs[w][lane >> 1];
        if (j >= 0) {
            float bj[9]; int fj[3];
            load_tri(verts, faces, j, bj, fj);           // L1/L2-hot by now
            acc = (lane & 1) ? cone_pen(bj, ri) : cone_pen(ri, bj);
        }
    }

    // ---- block reduce (fixed order) ----
#pragma unroll
    for (int off = 16; off > 0; off >>= 1)
        acc += __shfl_down_sync(0xffffffffu, acc, off);
    if (lane == 0) ssum[w] = acc;
    __syncthreads();
    if (t == 0) {
        float v = 0.0f;
#pragma unroll
        for (int q = 0; q < WPB; ++q) v += ssum[q];
        g_partial[blockIdx.x] = v;
        __threadfence();
        unsigned ticket = atomicAdd(&g_done, 1);
        bool last = (ticket == NBLK - 1);
        if (last) g_done = 0;                            // reset for next replay
        sLast = last;
    }
    __syncthreads();

    // ---- last finishing block: fixed-order final sum ----
    if (sLast) {
        float a = 0.0f;
        for (int b = t; b < NBLK; b += NT)               // fixed per-thread order
            a += g_partial[b];
        const int l2 = t & 31, w2 = t >> 5;
#pragma unroll
        for (int off = 16; off > 0; off >>= 1)
            a += __shfl_down_sync(0xffffffffu, a, off);
        __shared__ float fsum[WPB];
        if (l2 == 0) fsum[w2] = a;
        __syncthreads();
        if (t == 0) {
            float v = 0.0f;
#pragma unroll
            for (int q = 0; q < WPB; ++q) v += fsum[q];
            out[0] = v;
        }
    }
}

// ---------------- launch ----------------
extern "C" void kernel_launch(void* const* d_in, const int* in_sizes, int n_in,
                              void* d_out, int out_size) {
    const float* verts = (const float*)d_in[0];
    const int*   faces = (const int*)d_in[1];
    float* out = (float*)d_out;

    fused_kernel<<<NBLK, NT>>>(verts, faces, out);
}

// round 8
// speedup vs baseline: 1.9680x; 1.2142x over previous
#include <cuda_runtime.h>
#include <cuda_bf16.h>

#define NF   13776
#define KC   8
#define NT   256
#define WPB  (NT / 32)            // 8 receiver-warps per block
#define NBLK (NF / WPB)           // 1722 blocks, exact

// ---------------- scratch (device globals; no allocs) ----------------
__device__ float4   g_lo[NF];          // AABB min (w unused)
__device__ float4   g_hi[NF];          // AABB max (w unused)
__device__ int      g_f0[NF], g_f1[NF], g_f2[NF];
__device__ float4   g_tri4[NF * 3];    // vertex k of face f at [f*3+k], w unused
__device__ float    g_partial[NBLK];
__device__ unsigned g_done = 0;        // self-resetting ticket

__device__ __forceinline__ float min3(float a, float b, float c) { return fminf(a, fminf(b, c)); }
__device__ __forceinline__ float max3(float a, float b, float c) { return fmaxf(a, fmaxf(b, c)); }

// ---------------- kernel 1: build SoA AABBs + padded triangles ----------------
__global__ void __launch_bounds__(128)
setup_kernel(const float* __restrict__ verts,
             const int*   __restrict__ faces) {
    int f = blockIdx.x * 128 + threadIdx.x;
    if (f >= NF) return;

    int i0 = faces[3 * f + 0];
    int i1 = faces[3 * f + 1];
    int i2 = faces[3 * f + 2];

    float ax = verts[3 * i0 + 0], ay = verts[3 * i0 + 1], az = verts[3 * i0 + 2];
    float bx = verts[3 * i1 + 0], by = verts[3 * i1 + 1], bz = verts[3 * i1 + 2];
    float cx = verts[3 * i2 + 0], cy = verts[3 * i2 + 1], cz = verts[3 * i2 + 2];

    g_tri4[f * 3 + 0] = make_float4(ax, ay, az, 0.0f);
    g_tri4[f * 3 + 1] = make_float4(bx, by, bz, 0.0f);
    g_tri4[f * 3 + 2] = make_float4(cx, cy, cz, 0.0f);

    g_lo[f] = make_float4(min3(ax, bx, cx), min3(ay, by, cy), min3(az, bz, cz), 0.0f);
    g_hi[f] = make_float4(max3(ax, bx, cx), max3(ay, by, cy), max3(az, bz, cz), 0.0f);

    g_f0[f] = i0;
    g_f1[f] = i1;
    g_f2[f] = i2;
}

// ---------------- cone-field penalty (matches jnp fp32 math) ----------------
// SIGMA=0.5 -> r/SIGMA=2r, h/SIGMA=2h. POINT2PLANE=False, PENALIZE_OUTSIDE=True.
__device__ __forceinline__ float cone_pen(const float* __restrict__ s,
                                          const float* __restrict__ p) {
    float e0x = s[3] - s[0], e0y = s[4] - s[1], e0z = s[5] - s[2];
    float e1x = s[6] - s[0], e1y = s[7] - s[1], e1z = s[8] - s[2];
    float nx = e0y * e1z - e0z * e1y;
    float ny = e0z * e1x - e0x * e1z;
    float nz = e0x * e1y - e0y * e1x;
    float inv = 1.0f / (sqrtf(nx * nx + ny * ny + nz * nz) + 1e-8f);
    nx *= inv; ny *= inv; nz *= inv;
    float cx = (s[0] + s[3] + s[6]) * (1.0f / 3.0f);
    float cy = (s[1] + s[4] + s[7]) * (1.0f / 3.0f);
    float cz = (s[2] + s[5] + s[8]) * (1.0f / 3.0f);

    float acc = 0.0f;
#pragma unroll
    for (int v = 0; v < 3; ++v) {
        float ux = p[3 * v + 0] - cx;
        float uy = p[3 * v + 1] - cy;
        float uz = p[3 * v + 2] - cz;
        float h = ux * nx + uy * ny + uz * nz;
        float wx = ux - h * nx, wy = uy - h * ny, wz = uz - h * nz;
        float r = sqrtf(wx * wx + wy * wy + wz * wz);
        float radial = fmaxf(1.0f - 2.0f * r, 0.0f);
        float depth  = fmaxf(-h, 0.0f) + fmaxf(h, 0.0f) * __expf(-2.0f * h);
        float phi = radial * depth;
        acc += phi * phi;
    }
    return acc;
}

// ---------------- kernel 2: broad + narrow + full reduction ----------------
__global__ void __launch_bounds__(NT)
fused_kernel(float* __restrict__ out) {
    const int t    = threadIdx.x;
    const int lane = t & 31;
    const int w    = t >> 5;
    const int i    = blockIdx.x * WPB + w;       // receiver face, always < NF

    __shared__ int   sPairs[WPB][KC];
    __shared__ float ssum[WPB];
    __shared__ bool  sLast;

    // receiver state (broadcast loads — one sector per warp)
    float4 rlo = g_lo[i];
    float4 rhi = g_hi[i];
    int fi0 = g_f0[i], fi1 = g_f1[i], fi2 = g_f2[i];

    // ---- broad phase: warp ballot scan, first-KC ascending j ----
    int cnt = 0;
    for (int base = 0; base < NF && cnt < KC; base += 32) {
        int j = base + lane;
        bool ok = false;
        if (j < NF) {
            float4 jlo = g_lo[j];                // LDG.128 coalesced
            float4 jhi = g_hi[j];
            ok = (rlo.x <= jhi.x) & (jlo.x <= rhi.x) &
                 (rlo.y <= jhi.y) & (jlo.y <= rhi.y) &
                 (rlo.z <= jhi.z) & (jlo.z <= rhi.z);
            if (ok) {
                int j0 = g_f0[j], j1 = g_f1[j], j2 = g_f2[j];
                bool share = (fi0 == j0) | (fi0 == j1) | (fi0 == j2) |
                             (fi1 == j0) | (fi1 == j1) | (fi1 == j2) |
                             (fi2 == j0) | (fi2 == j1) | (fi2 == j2);
                ok = !share;
            }
        }
        unsigned m = __ballot_sync(0xffffffffu, ok);
        int rank = __popc(m & ((1u << lane) - 1u));
        if (ok && (cnt + rank) < KC)
            sPairs[w][cnt + rank] = j;
        cnt = min(KC, cnt + __popc(m));
    }
    if (lane < KC && lane >= cnt)
        sPairs[w][lane] = -1;
    __syncwarp();

    // ---- narrow phase: lane l<16 -> (pair l>>1, direction l&1) ----
    float acc = 0.0f;
    if (lane < 2 * KC) {
        int j = sPairs[w][lane >> 1];
        if (j >= 0) {
            float a[9], b[9];
            float4 v0 = g_tri4[i * 3 + 0], v1 = g_tri4[i * 3 + 1], v2 = g_tri4[i * 3 + 2];
            a[0] = v0.x; a[1] = v0.y; a[2] = v0.z;
            a[3] = v1.x; a[4] = v1.y; a[5] = v1.z;
            a[6] = v2.x; a[7] = v2.y; a[8] = v2.z;
            float4 u0 = g_tri4[j * 3 + 0], u1 = g_tri4[j * 3 + 1], u2 = g_tri4[j * 3 + 2];
            b[0] = u0.x; b[1] = u0.y; b[2] = u0.z;
            b[3] = u1.x; b[4] = u1.y; b[5] = u1.z;
            b[6] = u2.x; b[7] = u2.y; b[8] = u2.z;
            acc = (lane & 1) ? cone_pen(b, a) : cone_pen(a, b);
        }
    }

    // ---- block reduce (fixed order) ----
#pragma unroll
    for (int off = 16; off > 0; off >>= 1)
        acc += __shfl_down_sync(0xffffffffu, acc, off);
    if (lane == 0) ssum[w] = acc;
    __syncthreads();
    if (t == 0) {
        float v = 0.0f;
#pragma unroll
        for (int q = 0; q < WPB; ++q) v += ssum[q];
        g_partial[blockIdx.x] = v;
        __threadfence();
        unsigned ticket = atomicAdd(&g_done, 1);
        bool last = (ticket == NBLK - 1);
        if (last) g_done = 0;                    // reset for next graph replay
        sLast = last;
    }
    __syncthreads();

    // ---- last finishing block: fixed-order final sum ----
    if (sLast) {
        float a = 0.0f;
        for (int b = t; b < NBLK; b += NT)
            a += g_partial[b];
#pragma unroll
        for (int off = 16; off > 0; off >>= 1)
            a += __shfl_down_sync(0xffffffffu, a, off);
        __shared__ float fsum[WPB];
        if (lane == 0) fsum[w] = a;
        __syncthreads();
        if (t == 0) {
            float v = 0.0f;
#pragma unroll
            for (int q = 0; q < WPB; ++q) v += fsum[q];
            out[0] = v;
        }
    }
}

// ---------------- launch ----------------
extern "C" void kernel_launch(void* const* d_in, const int* in_sizes, int n_in,
                              void* d_out, int out_size) {
    const float* verts = (const float*)d_in[0];
    const int*   faces = (const int*)d_in[1];
    float* out = (float*)d_out;

    setup_kernel<<<(NF + 127) / 128, 128>>>(verts, faces);
    fused_kernel<<<NBLK, NT>>>(out);
}

// round 9
// speedup vs baseline: 2.2102x; 1.1231x over previous
#include <cuda_runtime.h>
#include <cuda_bf16.h>

#define NF   13776
#define KC   8
#define NT   256
#define RPB  16                   // receivers per block (2 per warp)
#define NBLK (NF / RPB)           // 861 blocks, exact (13776 = 861*16)

// ---------------- scratch (device globals; no allocs) ----------------
__device__ float4   g_lo[NF];          // AABB min; .w = face id0 (bits)
__device__ float4   g_hi[NF];          // AABB max; .w = face id1 (bits)
__device__ int      g_fc2[NF];         // face id2
__device__ float4   g_tri4[NF * 3];    // vertex k of face f at [f*3+k]
__device__ float    g_partial[NBLK];
__device__ unsigned g_done = 0;        // self-resetting ticket

__device__ __forceinline__ float min3(float a, float b, float c) { return fminf(a, fminf(b, c)); }
__device__ __forceinline__ float max3(float a, float b, float c) { return fmaxf(a, fmaxf(b, c)); }

// ---------------- kernel 1: build SoA AABBs + packed ids + triangles ----------------
__global__ void __launch_bounds__(256)
setup_kernel(const float* __restrict__ verts,
             const int*   __restrict__ faces) {
    int f = blockIdx.x * 256 + threadIdx.x;
    if (f >= NF) return;

    int i0 = faces[3 * f + 0];
    int i1 = faces[3 * f + 1];
    int i2 = faces[3 * f + 2];

    float ax = verts[3 * i0 + 0], ay = verts[3 * i0 + 1], az = verts[3 * i0 + 2];
    float bx = verts[3 * i1 + 0], by = verts[3 * i1 + 1], bz = verts[3 * i1 + 2];
    float cx = verts[3 * i2 + 0], cy = verts[3 * i2 + 1], cz = verts[3 * i2 + 2];

    g_tri4[f * 3 + 0] = make_float4(ax, ay, az, 0.0f);
    g_tri4[f * 3 + 1] = make_float4(bx, by, bz, 0.0f);
    g_tri4[f * 3 + 2] = make_float4(cx, cy, cz, 0.0f);

    g_lo[f] = make_float4(min3(ax, bx, cx), min3(ay, by, cy), min3(az, bz, cz),
                          __int_as_float(i0));
    g_hi[f] = make_float4(max3(ax, bx, cx), max3(ay, by, cy), max3(az, bz, cz),
                          __int_as_float(i1));
    g_fc2[f] = i2;
}

// ---------------- cone-field penalty (matches jnp fp32 math) ----------------
// SIGMA=0.5 -> r/SIGMA=2r, h/SIGMA=2h. POINT2PLANE=False, PENALIZE_OUTSIDE=True.
__device__ __forceinline__ float cone_pen(const float* __restrict__ s,
                                          const float* __restrict__ p) {
    float e0x = s[3] - s[0], e0y = s[4] - s[1], e0z = s[5] - s[2];
    float e1x = s[6] - s[0], e1y = s[7] - s[1], e1z = s[8] - s[2];
    float nx = e0y * e1z - e0z * e1y;
    float ny = e0z * e1x - e0x * e1z;
    float nz = e0x * e1y - e0y * e1x;
    float inv = 1.0f / (sqrtf(nx * nx + ny * ny + nz * nz) + 1e-8f);
    nx *= inv; ny *= inv; nz *= inv;
    float cx = (s[0] + s[3] + s[6]) * (1.0f / 3.0f);
    float cy = (s[1] + s[4] + s[7]) * (1.0f / 3.0f);
    float cz = (s[2] + s[5] + s[8]) * (1.0f / 3.0f);

    float acc = 0.0f;
#pragma unroll
    for (int v = 0; v < 3; ++v) {
        float ux = p[3 * v + 0] - cx;
        float uy = p[3 * v + 1] - cy;
        float uz = p[3 * v + 2] - cz;
        float h = ux * nx + uy * ny + uz * nz;
        float wx = ux - h * nx, wy = uy - h * ny, wz = uz - h * nz;
        float r = sqrtf(wx * wx + wy * wy + wz * wz);
        float radial = fmaxf(1.0f - 2.0f * r, 0.0f);
        float depth  = fmaxf(-h, 0.0f) + fmaxf(h, 0.0f) * __expf(-2.0f * h);
        float phi = radial * depth;
        acc += phi * phi;
    }
    return acc;
}

// ---------------- kernel 2: broad (2 receivers/warp) + packed narrow + reduce ----------------
__global__ void __launch_bounds__(NT)
fused_kernel(float* __restrict__ out) {
    const int t    = threadIdx.x;
    const int lane = t & 31;
    const int w    = t >> 5;
    const int blockBase = blockIdx.x * RPB;
    const int iA = blockBase + 2 * w;        // receiver A of this warp
    const int iB = iA + 1;                   // receiver B

    __shared__ int   sPairs[RPB][KC];
    __shared__ float ssum[NT / 32];
    __shared__ bool  sLast;

    // receiver state (broadcast loads)
    float4 rloA = g_lo[iA], rhiA = g_hi[iA];
    float4 rloB = g_lo[iB], rhiB = g_hi[iB];
    int a0 = __float_as_int(rloA.w), a1 = __float_as_int(rhiA.w), a2 = g_fc2[iA];
    int b0 = __float_as_int(rloB.w), b1 = __float_as_int(rhiB.w), b2 = g_fc2[iB];

    // ---- broad phase: shared load stream, two ballot streams ----
    int cntA = 0, cntB = 0;
    for (int base = 0; base < NF && (cntA < KC || cntB < KC); base += 32) {
        int j = base + lane;                 // NF not multiple of 32: guard below
        bool okA = false, okB = false;
        if (j < NF) {
            float4 jlo = g_lo[j];            // LDG.128 coalesced
            float4 jhi = g_hi[j];
            int j0 = __float_as_int(jlo.w);
            int j1 = __float_as_int(jhi.w);
            int j2 = g_fc2[j];

            okA = (rloA.x <= jhi.x) & (jlo.x <= rhiA.x) &
                  (rloA.y <= jhi.y) & (jlo.y <= rhiA.y) &
                  (rloA.z <= jhi.z) & (jlo.z <= rhiA.z);
            okB = (rloB.x <= jhi.x) & (jlo.x <= rhiB.x) &
                  (rloB.y <= jhi.y) & (jlo.y <= rhiB.y) &
                  (rloB.z <= jhi.z) & (jlo.z <= rhiB.z);
            if (okA) {
                bool sh = (a0 == j0) | (a0 == j1) | (a0 == j2) |
                          (a1 == j0) | (a1 == j1) | (a1 == j2) |
                          (a2 == j0) | (a2 == j1) | (a2 == j2);
                okA = !sh;
            }
            if (okB) {
                bool sh = (b0 == j0) | (b0 == j1) | (b0 == j2) |
                          (b1 == j0) | (b1 == j1) | (b1 == j2) |
                          (b2 == j0) | (b2 == j1) | (b2 == j2);
                okB = !sh;
            }
        }
        unsigned mA = __ballot_sync(0xffffffffu, okA);
        unsigned mB = __ballot_sync(0xffffffffu, okB);
        unsigned lt = (1u << lane) - 1u;
        int rkA = __popc(mA & lt);
        int rkB = __popc(mB & lt);
        if (okA && (cntA + rkA) < KC) sPairs[2 * w + 0][cntA + rkA] = j;
        if (okB && (cntB + rkB) < KC) sPairs[2 * w + 1][cntB + rkB] = j;
        cntA = min(KC, cntA + __popc(mA));
        cntB = min(KC, cntB + __popc(mB));
    }
    if (lane < KC) {
        if (lane >= cntA) sPairs[2 * w + 0][lane] = -1;
        if (lane >= cntB) sPairs[2 * w + 1][lane] = -1;
    }
    __syncthreads();

    // ---- narrow phase: 256 tasks, one per thread (full lane occupancy) ----
    // task t: receiver slot r = t>>4, pair k = (t>>1)&7, direction = t&1
    float acc = 0.0f;
    {
        int r = t >> 4;
        int k = (t >> 1) & 7;
        int i = blockBase + r;
        int j = sPairs[r][k];
        if (j >= 0) {
            float a[9], b[9];
            float4 v0 = g_tri4[i * 3 + 0], v1 = g_tri4[i * 3 + 1], v2 = g_tri4[i * 3 + 2];
            a[0] = v0.x; a[1] = v0.y; a[2] = v0.z;
            a[3] = v1.x; a[4] = v1.y; a[5] = v1.z;
            a[6] = v2.x; a[7] = v2.y; a[8] = v2.z;
            float4 u0 = g_tri4[j * 3 + 0], u1 = g_tri4[j * 3 + 1], u2 = g_tri4[j * 3 + 2];
            b[0] = u0.x; b[1] = u0.y; b[2] = u0.z;
            b[3] = u1.x; b[4] = u1.y; b[5] = u1.z;
            b[6] = u2.x; b[7] = u2.y; b[8] = u2.z;
            acc = (t & 1) ? cone_pen(b, a) : cone_pen(a, b);
        }
    }

    // ---- block reduce (fixed order) ----
#pragma unroll
    for (int off = 16; off > 0; off >>= 1)
        acc += __shfl_down_sync(0xffffffffu, acc, off);
    if (lane == 0) ssum[w] = acc;
    __syncthreads();
    if (t == 0) {
        float v = 0.0f;
#pragma unroll
        for (int q = 0; q < NT / 32; ++q) v += ssum[q];
        g_partial[blockIdx.x] = v;
        __threadfence();
        unsigned ticket = atomicAdd(&g_done, 1);
        bool last = (ticket == NBLK - 1);
        if (last) g_done = 0;                // reset for next graph replay
        sLast = last;
    }
    __syncthreads();

    // ---- last finishing block: fixed-order final sum ----
    if (sLast) {
        float a = 0.0f;
        for (int b = t; b < NBLK; b += NT)
            a += g_partial[b];
#pragma unroll
        for (int off = 16; off > 0; off >>= 1)
            a += __shfl_down_sync(0xffffffffu, a, off);
        __shared__ float fsum[NT / 32];
        if (lane == 0) fsum[w] = a;
        __syncthreads();
        if (t == 0) {
            float v = 0.0f;
#pragma unroll
            for (int q = 0; q < NT / 32; ++q) v += fsum[q];
            out[0] = v;
        }
    }
}

// ---------------- launch ----------------
extern "C" void kernel_launch(void* const* d_in, const int* in_sizes, int n_in,
                              void* d_out, int out_size) {
    const float* verts = (const float*)d_in[0];
    const int*   faces = (const int*)d_in[1];
    float* out = (float*)d_out;

    setup_kernel<<<(NF + 255) / 256, 256>>>(verts, faces);
    fused_kernel<<<NBLK, NT>>>(out);
}